// round 9
// baseline (speedup 1.0000x reference)
#include <cuda_runtime.h>
#include <cuda_bf16.h>
#include <math.h>

#define TT    100000
#define HDIM  16
#define UDIM  7
#define HID   64
#define XDIM  (HDIM + UDIM)

// Scratch (static device globals — no runtime allocation).
__device__ float g_V[(TT + 1) * HID];        // V[t][j] = b1[j] + W1_u[j] . u_t
__device__ float g_htraj[(TT + 1) * HDIM];   // h_t trajectory (h_traj[0] = h0)

// ---------------------------------------------------------------------------
// Kernel 1: precompute V[t][j] = b1[j] + sum_c W1[j][HDIM+c] * U[t][c]
// ---------------------------------------------------------------------------
__global__ void pre_kernel(const float* __restrict__ U,
                           const float* __restrict__ W1,
                           const float* __restrict__ b1) {
    int j = threadIdx.x;
    int t = blockIdx.x * blockDim.y + threadIdx.y;
    if (t >= TT) return;
    float acc = b1[j];
    const float* u = U + t * UDIM;
    const float* w = W1 + j * XDIM + HDIM;
#pragma unroll
    for (int c = 0; c < UDIM; c++)
        acc += w[c] * __ldg(u + c);
    g_V[t * HID + j] = acc;
}

// ---------------------------------------------------------------------------
// Kernel 2: sequential scan. One CTA, 128 threads (4 warps).
// Thread = (j = tid>>1, half = tid&1). z1 computed redundantly per half
// (16 FFMA); z2 GEMV is column-half-split (8 LDS.128 + 32 FFMA) with a
// single warp-internal shfl_xor(1) combine. dh identical to R1, on warps 0-1.
// z1s is padded (+4 floats between halves) so the two half-regions hit
// disjoint smem banks in the split GEMV read.
// ---------------------------------------------------------------------------
__global__ void __launch_bounds__(128, 1)
scan_kernel(const float* __restrict__ W1,
            const float* __restrict__ W2,
            const float* __restrict__ b2,
            const float* __restrict__ W3,
            const float* __restrict__ b3,
            const float* __restrict__ h0,
            float* __restrict__ out) {
    const int tid  = threadIdx.x;
    const int j    = tid >> 1;          // hidden unit 0..63
    const int half = tid & 1;           // which 32-col half of the GEMV
    const int i16  = tid >> 2;          // dh output (valid for tid<64)
    const int q    = tid & 3;           // dh quarter  (valid for tid<64)

    __shared__ __align__(16) float z1s[HID + 8];   // halves at 0 and 36
    __shared__ __align__(16) float z2s[HID];
    __shared__ __align__(16) float hs[HDIM];

    const float dt = (float)(5.0 / 60.0);

    // --- register-resident weights ---
    float w1h[HDIM];
#pragma unroll
    for (int c = 0; c < HDIM; c++) w1h[c] = W1[j * XDIM + c];

    float w2h[32];                       // W2 row j, this thread's column half
#pragma unroll
    for (int m = 0; m < 32; m++) w2h[m] = W2[j * HID + 32 * half + m];
    const float b2j = b2[j];

    float w3q[16];                       // dh weights (warps 0-1 only), dt folded
    float b3i = 0.0f;
    if (tid < 64) {
#pragma unroll
        for (int m = 0; m < 16; m++) w3q[m] = dt * W3[i16 * HID + q * 16 + m];
        if (q == 0) b3i = dt * b3[i16];
    }

    float h[HDIM];
#pragma unroll
    for (int c = 0; c < HDIM; c++) h[c] = h0[c];

    if (tid < HDIM) g_htraj[tid] = h[tid];

    const float* vp = g_V + HID + j;     // V[t+1][j] (both halves dup-load)
    float vcur = g_V[j];

#pragma unroll 1
    for (int t = 0; t < TT; t++) {
        float vnext = __ldg(vp);         // consumed next iteration
        vp += HID;

        // ---- z1 = tanh(W1_h . h + V[t][j])  (redundant per half) ----
        float a0 = vcur, a1 = 0.f, a2 = 0.f, a3 = 0.f;
#pragma unroll
        for (int c = 0; c < HDIM; c += 4) {
            a0 += w1h[c + 0] * h[c + 0];
            a1 += w1h[c + 1] * h[c + 1];
            a2 += w1h[c + 2] * h[c + 2];
            a3 += w1h[c + 3] * h[c + 3];
        }
        if (!half) z1s[j + (j >= 32 ? 4 : 0)] = tanhf((a0 + a1) + (a2 + a3));
        __syncthreads();                 // BAR-A

        // ---- z2 = tanh(W2 . z1 + b2), half-split columns ----
        float c0 = 0.f, c1 = 0.f, c2 = 0.f, c3 = 0.f;
        const float4* z14 = (const float4*)(z1s + 36 * half);
#pragma unroll
        for (int m = 0; m < 8; m += 4) {
            float4 x0 = z14[m], x1 = z14[m + 1], x2 = z14[m + 2], x3 = z14[m + 3];
            c0 += w2h[4*m+0]*x0.x  + w2h[4*m+1]*x0.y  + w2h[4*m+2]*x0.z  + w2h[4*m+3]*x0.w;
            c1 += w2h[4*m+4]*x1.x  + w2h[4*m+5]*x1.y  + w2h[4*m+6]*x1.z  + w2h[4*m+7]*x1.w;
            c2 += w2h[4*m+8]*x2.x  + w2h[4*m+9]*x2.y  + w2h[4*m+10]*x2.z + w2h[4*m+11]*x2.w;
            c3 += w2h[4*m+12]*x3.x + w2h[4*m+13]*x3.y + w2h[4*m+14]*x3.z + w2h[4*m+15]*x3.w;
        }
        float acc = (c0 + c1) + (c2 + c3);
        acc += __shfl_xor_sync(0xffffffffu, acc, 1);   // combine halves (pair in-warp)
        if (!half) z2s[j] = tanhf(acc + b2j);
        __syncthreads();                 // BAR-B

        // ---- dh (warps 0-1, warp-uniform guard): as in R1 ----
        if (tid < 64) {
            float p0 = b3i, p1 = 0.f, p2 = 0.f, p3 = 0.f;
            const float4* z24 = (const float4*)(z2s + q * 16);
            float4 x0 = z24[0], x1 = z24[1], x2 = z24[2], x3 = z24[3];
            p0 += w3q[0]*x0.x  + w3q[1]*x0.y  + w3q[2]*x0.z  + w3q[3]*x0.w;
            p1 += w3q[4]*x1.x  + w3q[5]*x1.y  + w3q[6]*x1.z  + w3q[7]*x1.w;
            p2 += w3q[8]*x2.x  + w3q[9]*x2.y  + w3q[10]*x2.z + w3q[11]*x2.w;
            p3 += w3q[12]*x3.x + w3q[13]*x3.y + w3q[14]*x3.z + w3q[15]*x3.w;
            float p = (p0 + p1) + (p2 + p3);
            p += __shfl_xor_sync(0xffffffffu, p, 1);
            p += __shfl_xor_sync(0xffffffffu, p, 2);
            if (q == 0) {
                float hn = h[i16] + p;
                hs[i16] = hn;
                g_htraj[(t + 1) * HDIM + i16] = hn;    // fire-and-forget
            }
        }
        __syncthreads();                 // BAR-C

        // ---- broadcast h back to all lanes ----
        const float4* h4 = (const float4*)hs;
#pragma unroll
        for (int c = 0; c < 4; c++) {
            float4 hv = h4[c];
            h[4 * c + 0] = hv.x;
            h[4 * c + 1] = hv.y;
            h[4 * c + 2] = hv.z;
            h[4 * c + 3] = hv.w;
        }
        vcur = vnext;
    }

    if (tid < HDIM) out[3 * TT + tid] = h[tid];
}

// ---------------------------------------------------------------------------
// Kernel 3: readouts from the stored trajectory.
// ---------------------------------------------------------------------------
__global__ void readout_kernel(const float* __restrict__ wd, const float* __restrict__ bd,
                               const float* __restrict__ wt, const float* __restrict__ bt,
                               const float* __restrict__ wc, const float* __restrict__ bc,
                               float* __restrict__ out) {
    int t = blockIdx.x * blockDim.x + threadIdx.x;
    if (t >= TT) return;

    float vd[HDIM], vt[HDIM], vc[HDIM];
#pragma unroll
    for (int k = 0; k < HDIM; k++) {
        vd[k] = __ldg(wd + k);
        vt[k] = __ldg(wt + k);
        vc[k] = __ldg(wc + k);
    }
    float d = __ldg(bd), x = __ldg(bt), c = __ldg(bc);
    const float4* h4 = (const float4*)(g_htraj + t * HDIM);
#pragma unroll
    for (int k = 0; k < 4; k++) {
        float4 hv = h4[k];
        d += hv.x * vd[4 * k] + hv.y * vd[4 * k + 1] + hv.z * vd[4 * k + 2] + hv.w * vd[4 * k + 3];
        x += hv.x * vt[4 * k] + hv.y * vt[4 * k + 1] + hv.z * vt[4 * k + 2] + hv.w * vt[4 * k + 3];
        c += hv.x * vc[4 * k] + hv.y * vc[4 * k + 1] + hv.z * vc[4 * k + 2] + hv.w * vc[4 * k + 3];
    }
    out[t]          = d;
    out[TT + t]     = x;
    out[2 * TT + t] = c;
}

// ---------------------------------------------------------------------------
extern "C" void kernel_launch(void* const* d_in, const int* in_sizes, int n_in,
                              void* d_out, int out_size) {
    const float* U  = (const float*)d_in[0];
    const float* W1 = (const float*)d_in[1];
    const float* b1 = (const float*)d_in[2];
    const float* W2 = (const float*)d_in[3];
    const float* b2 = (const float*)d_in[4];
    const float* W3 = (const float*)d_in[5];
    const float* b3 = (const float*)d_in[6];
    const float* wd = (const float*)d_in[7];
    const float* bd = (const float*)d_in[8];
    const float* wt = (const float*)d_in[9];
    const float* bt = (const float*)d_in[10];
    const float* wc = (const float*)d_in[11];
    const float* bc = (const float*)d_in[12];
    const float* h0 = (const float*)d_in[13];
    float* out = (float*)d_out;

    dim3 pb(HID, 4);
    pre_kernel<<<(TT + 3) / 4, pb>>>(U, W1, b1);
    scan_kernel<<<1, 128>>>(W1, W2, b2, W3, b3, h0, out);
    readout_kernel<<<(TT + 127) / 128, 128>>>(wd, bd, wt, bt, wc, bc, out);
}

// round 10
// speedup vs baseline: 1.1773x; 1.1773x over previous
#include <cuda_runtime.h>
#include <cuda_bf16.h>
#include <math.h>

#define TT    100000
#define HDIM  16
#define UDIM  7
#define HID   64
#define XDIM  (HDIM + UDIM)

// Scratch (static device globals — no runtime allocation).
__device__ float g_V[(TT + 1) * HID];        // V[t][j] = b1[j] + W1_u[j] . u_t
__device__ float g_htraj[(TT + 1) * HDIM];   // h_t trajectory (h_traj[0] = h0)

// ---------------------------------------------------------------------------
// Kernel 1: precompute V[t][j] = b1[j] + sum_c W1[j][HDIM+c] * U[t][c]
// ---------------------------------------------------------------------------
__global__ void pre_kernel(const float* __restrict__ U,
                           const float* __restrict__ W1,
                           const float* __restrict__ b1) {
    int j = threadIdx.x;
    int t = blockIdx.x * blockDim.y + threadIdx.y;
    if (t >= TT) return;
    float acc = b1[j];
    const float* u = U + t * UDIM;
    const float* w = W1 + j * XDIM + HDIM;
#pragma unroll
    for (int c = 0; c < UDIM; c++)
        acc += w[c] * __ldg(u + c);
    g_V[t * HID + j] = acc;
}

// ---------------------------------------------------------------------------
// Kernel 2: sequential scan. One CTA, 64 threads (2 warps), 2 barriers/step.
// Lane j owns hidden unit j for z1/z2 (as R1). After BAR-B each warp
// REDUNDANTLY computes all 16 h-updates (2 lanes/output, 32 MACs each,
// one shfl_xor combine) into a warp-private hs row — cross-warp BAR-C is
// replaced by __syncwarp. Both warps produce bitwise-identical h.
// ---------------------------------------------------------------------------
__global__ void __launch_bounds__(64, 1)
scan_kernel(const float* __restrict__ W1,
            const float* __restrict__ W2,
            const float* __restrict__ b2,
            const float* __restrict__ W3,
            const float* __restrict__ b3,
            const float* __restrict__ h0,
            float* __restrict__ out) {
    const int j    = threadIdx.x;
    const int w    = j >> 5;           // warp id
    const int lane = j & 31;
    const int oi   = lane >> 1;        // dh output index 0..15
    const int oh   = lane & 1;         // which 32-col half of W3 row

    __shared__ __align__(16) float z1s[HID];
    __shared__ __align__(16) float z2s[HID];
    __shared__ __align__(16) float hs[2][HDIM];   // warp-private h copies

    const float dt = (float)(5.0 / 60.0);

    // --- register-resident weights (one-time) ---
    float w1h[HDIM];
#pragma unroll
    for (int c = 0; c < HDIM; c++) w1h[c] = W1[j * XDIM + c];

    float w2r[HID];
#pragma unroll
    for (int c = 0; c < HID; c++) w2r[c] = W2[j * HID + c];
    const float b2j = b2[j];

    float w3d[32];                      // dt * W3[oi][oh*32 .. oh*32+31]
#pragma unroll
    for (int m = 0; m < 32; m++)
        w3d[m] = dt * W3[oi * HID + oh * 32 + m];
    const float b3i = (oh == 0) ? dt * b3[oi] : 0.0f;

    float h[HDIM];
#pragma unroll
    for (int c = 0; c < HDIM; c++) h[c] = h0[c];

    if (j < HDIM) g_htraj[j] = h[j];

    const float* vp = g_V + HID + j;
    float vcur = g_V[j];

#pragma unroll 2
    for (int t = 0; t < TT; t++) {
        float vnext = __ldg(vp);        // consumed next iteration
        vp += HID;

        // ---- z1 = tanh(W1_h . h + V[t][j]) ----
        float a0 = vcur, a1 = 0.f, a2 = 0.f, a3 = 0.f;
#pragma unroll
        for (int c = 0; c < HDIM; c += 4) {
            a0 += w1h[c + 0] * h[c + 0];
            a1 += w1h[c + 1] * h[c + 1];
            a2 += w1h[c + 2] * h[c + 2];
            a3 += w1h[c + 3] * h[c + 3];
        }
        z1s[j] = tanhf((a0 + a1) + (a2 + a3));
        __syncthreads();                // BAR-A (also fences dh's z2s reads of t-1)

        // ---- z2 = tanh(W2 . z1 + b2) ----
        float c0 = b2j, c1 = 0.f, c2 = 0.f, c3 = 0.f;
        const float4* z14 = (const float4*)z1s;
#pragma unroll
        for (int c = 0; c < 16; c++) {
            float4 z = z14[c];
            c0 += w2r[4 * c + 0] * z.x;
            c1 += w2r[4 * c + 1] * z.y;
            c2 += w2r[4 * c + 2] * z.z;
            c3 += w2r[4 * c + 3] * z.w;
        }
        z2s[j] = tanhf((c0 + c1) + (c2 + c3));
        __syncthreads();                // BAR-B (also fences z2's z1s reads)

        // ---- per-warp redundant dh: output oi, 32-col half oh ----
        float p0 = b3i, p1 = 0.f, p2 = 0.f, p3 = 0.f;
        const float4* zz = (const float4*)(z2s + oh * 32);
#pragma unroll
        for (int m = 0; m < 8; m += 4) {
            float4 x0 = zz[m], x1 = zz[m + 1], x2 = zz[m + 2], x3 = zz[m + 3];
            p0 += w3d[4*m+0]*x0.x  + w3d[4*m+1]*x0.y  + w3d[4*m+2]*x0.z  + w3d[4*m+3]*x0.w;
            p1 += w3d[4*m+4]*x1.x  + w3d[4*m+5]*x1.y  + w3d[4*m+6]*x1.z  + w3d[4*m+7]*x1.w;
            p2 += w3d[4*m+8]*x2.x  + w3d[4*m+9]*x2.y  + w3d[4*m+10]*x2.z + w3d[4*m+11]*x2.w;
            p3 += w3d[4*m+12]*x3.x + w3d[4*m+13]*x3.y + w3d[4*m+14]*x3.z + w3d[4*m+15]*x3.w;
        }
        float p = (p0 + p1) + (p2 + p3);
        p += __shfl_xor_sync(0xffffffffu, p, 1);   // combine the two halves
        if (oh == 0) {
            float hn = h[oi] + p;
            hs[w][oi] = hn;
            if (w == 0) g_htraj[(t + 1) * HDIM + oi] = hn;  // fire-and-forget
        }
        __syncwarp();                   // hs[w] is warp-private

        // ---- reload h from this warp's private copy ----
        const float4* h4 = (const float4*)hs[w];
#pragma unroll
        for (int c = 0; c < 4; c++) {
            float4 hv = h4[c];
            h[4 * c + 0] = hv.x;
            h[4 * c + 1] = hv.y;
            h[4 * c + 2] = hv.z;
            h[4 * c + 3] = hv.w;
        }
        vcur = vnext;
    }

    if (j < HDIM) out[3 * TT + j] = h[j];
}

// ---------------------------------------------------------------------------
// Kernel 3: readouts from the stored trajectory.
// ---------------------------------------------------------------------------
__global__ void readout_kernel(const float* __restrict__ wd, const float* __restrict__ bd,
                               const float* __restrict__ wt, const float* __restrict__ bt,
                               const float* __restrict__ wc, const float* __restrict__ bc,
                               float* __restrict__ out) {
    int t = blockIdx.x * blockDim.x + threadIdx.x;
    if (t >= TT) return;

    float vd[HDIM], vt[HDIM], vc[HDIM];
#pragma unroll
    for (int k = 0; k < HDIM; k++) {
        vd[k] = __ldg(wd + k);
        vt[k] = __ldg(wt + k);
        vc[k] = __ldg(wc + k);
    }
    float d = __ldg(bd), x = __ldg(bt), c = __ldg(bc);
    const float4* h4 = (const float4*)(g_htraj + t * HDIM);
#pragma unroll
    for (int k = 0; k < 4; k++) {
        float4 hv = h4[k];
        d += hv.x * vd[4 * k] + hv.y * vd[4 * k + 1] + hv.z * vd[4 * k + 2] + hv.w * vd[4 * k + 3];
        x += hv.x * vt[4 * k] + hv.y * vt[4 * k + 1] + hv.z * vt[4 * k + 2] + hv.w * vt[4 * k + 3];
        c += hv.x * vc[4 * k] + hv.y * vc[4 * k + 1] + hv.z * vc[4 * k + 2] + hv.w * vc[4 * k + 3];
    }
    out[t]          = d;
    out[TT + t]     = x;
    out[2 * TT + t] = c;
}

// ---------------------------------------------------------------------------
extern "C" void kernel_launch(void* const* d_in, const int* in_sizes, int n_in,
                              void* d_out, int out_size) {
    const float* U  = (const float*)d_in[0];
    const float* W1 = (const float*)d_in[1];
    const float* b1 = (const float*)d_in[2];
    const float* W2 = (const float*)d_in[3];
    const float* b2 = (const float*)d_in[4];
    const float* W3 = (const float*)d_in[5];
    const float* b3 = (const float*)d_in[6];
    const float* wd = (const float*)d_in[7];
    const float* bd = (const float*)d_in[8];
    const float* wt = (const float*)d_in[9];
    const float* bt = (const float*)d_in[10];
    const float* wc = (const float*)d_in[11];
    const float* bc = (const float*)d_in[12];
    const float* h0 = (const float*)d_in[13];
    float* out = (float*)d_out;

    dim3 pb(HID, 4);
    pre_kernel<<<(TT + 3) / 4, pb>>>(U, W1, b1);
    scan_kernel<<<1, HID>>>(W1, W2, b2, W3, b3, h0, out);
    readout_kernel<<<(TT + 127) / 128, 128>>>(wd, bd, wt, bt, wc, bc, out);
}

// round 11
// speedup vs baseline: 1.5242x; 1.2947x over previous
#include <cuda_runtime.h>
#include <cuda_bf16.h>
#include <math.h>

#define TT    100000
#define HDIM  16
#define UDIM  7
#define HID   64
#define XDIM  (HDIM + UDIM)

// Scratch (static device globals — no runtime allocation).
__device__ float g_V[(TT + 1) * HID];        // V[t][j] = b1[j] + W1_u[j] . u_t
__device__ float g_htraj[(TT + 1) * HDIM];   // h_t trajectory (h_traj[0] = h0)

// ---------------------------------------------------------------------------
// Kernel 1: precompute V[t][j] = b1[j] + sum_c W1[j][HDIM+c] * U[t][c]
// Fully parallel over t. blockDim = (64, 4).
// ---------------------------------------------------------------------------
__global__ void pre_kernel(const float* __restrict__ U,
                           const float* __restrict__ W1,
                           const float* __restrict__ b1) {
    int j = threadIdx.x;                       // hidden unit 0..63
    int t = blockIdx.x * blockDim.y + threadIdx.y;
    if (t >= TT) return;
    float acc = b1[j];
    const float* u = U + t * UDIM;
    const float* w = W1 + j * XDIM + HDIM;
#pragma unroll
    for (int c = 0; c < UDIM; c++)
        acc += w[c] * __ldg(u + c);
    g_V[t * HID + j] = acc;
}

// ---------------------------------------------------------------------------
// Kernel 2: the sequential scan. One CTA, 64 threads (2 warps). Structure
// IDENTICAL to the measured-best R1 kernel (3 barriers, lane j owns unit j,
// dh split 4 lanes/output with 2-level butterfly). Only intra-phase changes:
//   - z2 dot product uses 8 accumulators (dependent chain 16->8 FFMAs)
//   - dt folded into w3q/b3i (one fewer FMUL on the h-update chain)
// ---------------------------------------------------------------------------
__global__ void __launch_bounds__(64, 1)
scan_kernel(const float* __restrict__ W1,
            const float* __restrict__ W2,
            const float* __restrict__ b2,
            const float* __restrict__ W3,
            const float* __restrict__ b3,
            const float* __restrict__ h0,
            float* __restrict__ out) {
    const int j   = threadIdx.x;
    const int q   = j & 3;
    const int i16 = j >> 2;

    __shared__ __align__(16) float z1s[HID];
    __shared__ __align__(16) float z2s[HID];
    __shared__ __align__(16) float hs[HDIM];

    const float dt = (float)(5.0 / 60.0);

    // --- load weights into registers (one-time) ---
    float w1h[HDIM];
#pragma unroll
    for (int c = 0; c < HDIM; c++) w1h[c] = W1[j * XDIM + c];

    float w2r[HID];
#pragma unroll
    for (int c = 0; c < HID; c++) w2r[c] = W2[j * HID + c];
    const float b2j = b2[j];

    float w3q[16];                                // dt pre-folded
#pragma unroll
    for (int m = 0; m < 16; m++) w3q[m] = dt * W3[i16 * HID + q * 16 + m];
    const float b3i = (q == 0) ? dt * b3[i16] : 0.0f;

    float h[HDIM];
#pragma unroll
    for (int c = 0; c < HDIM; c++) h[c] = h0[c];

    if (j < HDIM) g_htraj[j] = h[j];              // h_traj[0] = h0

    const float* vp = g_V + HID + j;              // points at V[t+1][j]
    float vcur = g_V[j];                          // V[0][j]

#pragma unroll 1
    for (int t = 0; t < TT; t++) {
        // prefetch next V early — consumed ~500 cycles later
        float vnext = __ldg(vp);
        vp += HID;

        // ---- z1 = tanh(W1_h . h + V[t][j]) ----
        float a0 = vcur, a1 = 0.f, a2 = 0.f, a3 = 0.f;
#pragma unroll
        for (int c = 0; c < HDIM; c += 4) {
            a0 += w1h[c + 0] * h[c + 0];
            a1 += w1h[c + 1] * h[c + 1];
            a2 += w1h[c + 2] * h[c + 2];
            a3 += w1h[c + 3] * h[c + 3];
        }
        float z1 = tanhf((a0 + a1) + (a2 + a3));
        z1s[j] = z1;
        __syncthreads();

        // ---- z2 = tanh(W2 . z1 + b2) ; 8 accumulators (shorter dep chain) ----
        float c0 = b2j, c1 = 0.f, c2 = 0.f, c3 = 0.f;
        float c4 = 0.f, c5 = 0.f, c6 = 0.f, c7 = 0.f;
        const float4* z14 = (const float4*)z1s;
#pragma unroll
        for (int c = 0; c < 16; c += 2) {
            float4 za = z14[c];
            float4 zb = z14[c + 1];
            c0 += w2r[4 * c + 0] * za.x;
            c1 += w2r[4 * c + 1] * za.y;
            c2 += w2r[4 * c + 2] * za.z;
            c3 += w2r[4 * c + 3] * za.w;
            c4 += w2r[4 * c + 4] * zb.x;
            c5 += w2r[4 * c + 5] * zb.y;
            c6 += w2r[4 * c + 6] * zb.z;
            c7 += w2r[4 * c + 7] * zb.w;
        }
        float z2 = tanhf(((c0 + c1) + (c2 + c3)) + ((c4 + c5) + (c6 + c7)));
        z2s[j] = z2;
        __syncthreads();

        // ---- dh[i16] partial over quarter q (dt folded), 4-lane butterfly ----
        float p0 = b3i, p1 = 0.f, p2 = 0.f, p3 = 0.f;
        const float4* z24 = (const float4*)(z2s + q * 16);
        {
            float4 x0 = z24[0], x1 = z24[1], x2 = z24[2], x3 = z24[3];
            p0 += w3q[0]*x0.x  + w3q[1]*x0.y  + w3q[2]*x0.z  + w3q[3]*x0.w;
            p1 += w3q[4]*x1.x  + w3q[5]*x1.y  + w3q[6]*x1.z  + w3q[7]*x1.w;
            p2 += w3q[8]*x2.x  + w3q[9]*x2.y  + w3q[10]*x2.z + w3q[11]*x2.w;
            p3 += w3q[12]*x3.x + w3q[13]*x3.y + w3q[14]*x3.z + w3q[15]*x3.w;
        }
        float p = (p0 + p1) + (p2 + p3);
        p += __shfl_xor_sync(0xffffffffu, p, 1);
        p += __shfl_xor_sync(0xffffffffu, p, 2);

        if (q == 0) {
            float hn = h[i16] + p;
            hs[i16] = hn;
            g_htraj[(t + 1) * HDIM + i16] = hn;   // fire-and-forget
        }
        __syncthreads();

        // ---- broadcast h back to all lanes ----
        const float4* h4 = (const float4*)hs;
#pragma unroll
        for (int c = 0; c < 4; c++) {
            float4 hv = h4[c];
            h[4 * c + 0] = hv.x;
            h[4 * c + 1] = hv.y;
            h[4 * c + 2] = hv.z;
            h[4 * c + 3] = hv.w;
        }
        vcur = vnext;
    }

    // final state hT -> out[3T .. 3T+16)
    if (j < HDIM) out[3 * TT + j] = h[j];
}

// ---------------------------------------------------------------------------
// Kernel 3: readouts from the stored trajectory. Fully parallel over t.
// ---------------------------------------------------------------------------
__global__ void readout_kernel(const float* __restrict__ wd, const float* __restrict__ bd,
                               const float* __restrict__ wt, const float* __restrict__ bt,
                               const float* __restrict__ wc, const float* __restrict__ bc,
                               float* __restrict__ out) {
    int t = blockIdx.x * blockDim.x + threadIdx.x;
    if (t >= TT) return;

    float vd[HDIM], vt[HDIM], vc[HDIM];
#pragma unroll
    for (int k = 0; k < HDIM; k++) {
        vd[k] = __ldg(wd + k);
        vt[k] = __ldg(wt + k);
        vc[k] = __ldg(wc + k);
    }
    float d = __ldg(bd), x = __ldg(bt), c = __ldg(bc);
    const float4* h4 = (const float4*)(g_htraj + t * HDIM);
#pragma unroll
    for (int k = 0; k < 4; k++) {
        float4 hv = h4[k];
        d += hv.x * vd[4 * k] + hv.y * vd[4 * k + 1] + hv.z * vd[4 * k + 2] + hv.w * vd[4 * k + 3];
        x += hv.x * vt[4 * k] + hv.y * vt[4 * k + 1] + hv.z * vt[4 * k + 2] + hv.w * vt[4 * k + 3];
        c += hv.x * vc[4 * k] + hv.y * vc[4 * k + 1] + hv.z * vc[4 * k + 2] + hv.w * vc[4 * k + 3];
    }
    out[t]          = d;
    out[TT + t]     = x;
    out[2 * TT + t] = c;
}

// ---------------------------------------------------------------------------
extern "C" void kernel_launch(void* const* d_in, const int* in_sizes, int n_in,
                              void* d_out, int out_size) {
    const float* U  = (const float*)d_in[0];
    const float* W1 = (const float*)d_in[1];
    const float* b1 = (const float*)d_in[2];
    const float* W2 = (const float*)d_in[3];
    const float* b2 = (const float*)d_in[4];
    const float* W3 = (const float*)d_in[5];
    const float* b3 = (const float*)d_in[6];
    const float* wd = (const float*)d_in[7];
    const float* bd = (const float*)d_in[8];
    const float* wt = (const float*)d_in[9];
    const float* bt = (const float*)d_in[10];
    const float* wc = (const float*)d_in[11];
    const float* bc = (const float*)d_in[12];
    const float* h0 = (const float*)d_in[13];
    float* out = (float*)d_out;

    dim3 pb(HID, 4);
    pre_kernel<<<(TT + 3) / 4, pb>>>(U, W1, b1);
    scan_kernel<<<1, HID>>>(W1, W2, b2, W3, b3, h0, out);
    readout_kernel<<<(TT + 127) / 128, 128>>>(wd, bd, wt, bt, wc, bc, out);
}

// round 12
// speedup vs baseline: 1.5329x; 1.0057x over previous
#include <cuda_runtime.h>
#include <cuda_bf16.h>
#include <math.h>

#define TT    100000
#define HDIM  16
#define UDIM  7
#define HID   64
#define XDIM  (HDIM + UDIM)

// Scratch (static device globals — no runtime allocation).
__device__ float g_V[(TT + 1) * HID];        // V[t][j] = b1[j] + W1_u[j] . u_t
__device__ float g_htraj[(TT + 1) * HDIM];   // h_t trajectory (h_traj[0] = h0)

// ---------------------------------------------------------------------------
// Kernel 1: precompute V[t][j] = b1[j] + sum_c W1[j][HDIM+c] * U[t][c]
// Fully parallel over t. blockDim = (64, 4).
// ---------------------------------------------------------------------------
__global__ void pre_kernel(const float* __restrict__ U,
                           const float* __restrict__ W1,
                           const float* __restrict__ b1) {
    int j = threadIdx.x;                       // hidden unit 0..63
    int t = blockIdx.x * blockDim.y + threadIdx.y;
    if (t >= TT) return;
    float acc = b1[j];
    const float* u = U + t * UDIM;
    const float* w = W1 + j * XDIM + HDIM;
#pragma unroll
    for (int c = 0; c < UDIM; c++)
        acc += w[c] * __ldg(u + c);
    g_V[t * HID + j] = acc;
}

// ---------------------------------------------------------------------------
// Kernel 2: sequential scan. One CTA, 64 threads (2 warps). Structure
// IDENTICAL to the measured-best R1 kernel (3 barriers, lane j owns unit j,
// z2 with 4 accumulators, dh split 4 lanes/output with 2-level butterfly).
// Changes vs R1 (zero added instructions):
//   - z2s stored with XOR swizzle  addr(e) = (e&~15) | ((e&15) ^ 4*(e>>4))
//     so the dh phase's 4 LDS.128 per lane are bank-conflict-free
//     (R1 layout provably 2-way conflicted on every dh load: q0/q2, q1/q3).
//     Reads: zz4[q^k] holds elements 4k..4k+3 of block q -> pairs w3q[4k..].
//   - dt folded into w3q/b3i (one fewer dependent FMUL in the h update).
// ---------------------------------------------------------------------------
__global__ void __launch_bounds__(64, 1)
scan_kernel(const float* __restrict__ W1,
            const float* __restrict__ W2,
            const float* __restrict__ b2,
            const float* __restrict__ W3,
            const float* __restrict__ b3,
            const float* __restrict__ h0,
            float* __restrict__ out) {
    const int j   = threadIdx.x;
    const int q   = j & 3;
    const int i16 = j >> 2;

    __shared__ __align__(16) float z1s[HID];
    __shared__ __align__(16) float z2s[HID];   // XOR-swizzled storage
    __shared__ __align__(16) float hs[HDIM];

    const float dt = (float)(5.0 / 60.0);

    // swizzled store index for this lane's z2 element j:
    // block b = j>>4 (16 elems), in-block offset (j&15) ^ (4b)
    const int z2idx = (j & 48) | ((j & 15) ^ ((j >> 2) & 12));

    // --- load weights into registers (one-time) ---
    float w1h[HDIM];
#pragma unroll
    for (int c = 0; c < HDIM; c++) w1h[c] = W1[j * XDIM + c];

    float w2r[HID];
#pragma unroll
    for (int c = 0; c < HID; c++) w2r[c] = W2[j * HID + c];
    const float b2j = b2[j];

    float w3q[16];                                // dt pre-folded
#pragma unroll
    for (int m = 0; m < 16; m++) w3q[m] = dt * W3[i16 * HID + q * 16 + m];
    const float b3i = (q == 0) ? dt * b3[i16] : 0.0f;

    float h[HDIM];
#pragma unroll
    for (int c = 0; c < HDIM; c++) h[c] = h0[c];

    if (j < HDIM) g_htraj[j] = h[j];              // h_traj[0] = h0

    const float* vp = g_V + HID + j;              // points at V[t+1][j]
    float vcur = g_V[j];                          // V[0][j]

#pragma unroll 1
    for (int t = 0; t < TT; t++) {
        // prefetch next V early — consumed ~500 cycles later
        float vnext = __ldg(vp);
        vp += HID;

        // ---- z1 = tanh(W1_h . h + V[t][j]) ----
        float a0 = vcur, a1 = 0.f, a2 = 0.f, a3 = 0.f;
#pragma unroll
        for (int c = 0; c < HDIM; c += 4) {
            a0 += w1h[c + 0] * h[c + 0];
            a1 += w1h[c + 1] * h[c + 1];
            a2 += w1h[c + 2] * h[c + 2];
            a3 += w1h[c + 3] * h[c + 3];
        }
        float z1 = tanhf((a0 + a1) + (a2 + a3));
        z1s[j] = z1;
        __syncthreads();

        // ---- z2 = tanh(W2 . z1 + b2) ----
        float c0 = b2j, c1 = 0.f, c2 = 0.f, c3 = 0.f;
        const float4* z14 = (const float4*)z1s;
#pragma unroll
        for (int c = 0; c < 16; c++) {
            float4 z = z14[c];
            c0 += w2r[4 * c + 0] * z.x;
            c1 += w2r[4 * c + 1] * z.y;
            c2 += w2r[4 * c + 2] * z.z;
            c3 += w2r[4 * c + 3] * z.w;
        }
        float z2 = tanhf((c0 + c1) + (c2 + c3));
        z2s[z2idx] = z2;                           // swizzled, conflict-free STS
        __syncthreads();

        // ---- dh[i16] partial over quarter q (dt folded), 4-lane butterfly ----
        // swizzled reads: zz4[q^k] = elements q*16 + 4k .. +3
        float p0 = b3i, p1 = 0.f, p2 = 0.f, p3 = 0.f;
        const float4* zz4 = (const float4*)(z2s + q * 16);
        {
            float4 x0 = zz4[q];                    // elements 0..3  of block q
            float4 x1 = zz4[q ^ 1];                // elements 4..7
            float4 x2 = zz4[q ^ 2];                // elements 8..11
            float4 x3 = zz4[q ^ 3];                // elements 12..15
            p0 += w3q[0]*x0.x  + w3q[1]*x0.y  + w3q[2]*x0.z  + w3q[3]*x0.w;
            p1 += w3q[4]*x1.x  + w3q[5]*x1.y  + w3q[6]*x1.z  + w3q[7]*x1.w;
            p2 += w3q[8]*x2.x  + w3q[9]*x2.y  + w3q[10]*x2.z + w3q[11]*x2.w;
            p3 += w3q[12]*x3.x + w3q[13]*x3.y + w3q[14]*x3.z + w3q[15]*x3.w;
        }
        float p = (p0 + p1) + (p2 + p3);
        p += __shfl_xor_sync(0xffffffffu, p, 1);
        p += __shfl_xor_sync(0xffffffffu, p, 2);

        if (q == 0) {
            float hn = h[i16] + p;
            hs[i16] = hn;
            g_htraj[(t + 1) * HDIM + i16] = hn;   // fire-and-forget
        }
        __syncthreads();

        // ---- broadcast h back to all lanes ----
        const float4* h4 = (const float4*)hs;
#pragma unroll
        for (int c = 0; c < 4; c++) {
            float4 hv = h4[c];
            h[4 * c + 0] = hv.x;
            h[4 * c + 1] = hv.y;
            h[4 * c + 2] = hv.z;
            h[4 * c + 3] = hv.w;
        }
        vcur = vnext;
    }

    // final state hT -> out[3T .. 3T+16)
    if (j < HDIM) out[3 * TT + j] = h[j];
}

// ---------------------------------------------------------------------------
// Kernel 3: readouts from the stored trajectory. Fully parallel over t.
// ---------------------------------------------------------------------------
__global__ void readout_kernel(const float* __restrict__ wd, const float* __restrict__ bd,
                               const float* __restrict__ wt, const float* __restrict__ bt,
                               const float* __restrict__ wc, const float* __restrict__ bc,
                               float* __restrict__ out) {
    int t = blockIdx.x * blockDim.x + threadIdx.x;
    if (t >= TT) return;

    float vd[HDIM], vt[HDIM], vc[HDIM];
#pragma unroll
    for (int k = 0; k < HDIM; k++) {
        vd[k] = __ldg(wd + k);
        vt[k] = __ldg(wt + k);
        vc[k] = __ldg(wc + k);
    }
    float d = __ldg(bd), x = __ldg(bt), c = __ldg(bc);
    const float4* h4 = (const float4*)(g_htraj + t * HDIM);
#pragma unroll
    for (int k = 0; k < 4; k++) {
        float4 hv = h4[k];
        d += hv.x * vd[4 * k] + hv.y * vd[4 * k + 1] + hv.z * vd[4 * k + 2] + hv.w * vd[4 * k + 3];
        x += hv.x * vt[4 * k] + hv.y * vt[4 * k + 1] + hv.z * vt[4 * k + 2] + hv.w * vt[4 * k + 3];
        c += hv.x * vc[4 * k] + hv.y * vc[4 * k + 1] + hv.z * vc[4 * k + 2] + hv.w * vc[4 * k + 3];
    }
    out[t]          = d;
    out[TT + t]     = x;
    out[2 * TT + t] = c;
}

// ---------------------------------------------------------------------------
extern "C" void kernel_launch(void* const* d_in, const int* in_sizes, int n_in,
                              void* d_out, int out_size) {
    const float* U  = (const float*)d_in[0];
    const float* W1 = (const float*)d_in[1];
    const float* b1 = (const float*)d_in[2];
    const float* W2 = (const float*)d_in[3];
    const float* b2 = (const float*)d_in[4];
    const float* W3 = (const float*)d_in[5];
    const float* b3 = (const float*)d_in[6];
    const float* wd = (const float*)d_in[7];
    const float* bd = (const float*)d_in[8];
    const float* wt = (const float*)d_in[9];
    const float* bt = (const float*)d_in[10];
    const float* wc = (const float*)d_in[11];
    const float* bc = (const float*)d_in[12];
    const float* h0 = (const float*)d_in[13];
    float* out = (float*)d_out;

    dim3 pb(HID, 4);
    pre_kernel<<<(TT + 3) / 4, pb>>>(U, W1, b1);
    scan_kernel<<<1, HID>>>(W1, W2, b2, W3, b3, h0, out);
    readout_kernel<<<(TT + 127) / 128, 128>>>(wd, bd, wt, bt, wc, bc, out);
}

// round 13
// speedup vs baseline: 1.5597x; 1.0175x over previous
#include <cuda_runtime.h>
#include <cuda_bf16.h>

#define TT    100000
#define HDIM  16
#define UDIM  7
#define HID   64
#define XDIM  (HDIM + UDIM)

// Scratch (static device globals — no allocation at runtime).
__device__ float g_V[(TT + 1) * HID];        // V[t][j] = b1[j] + W1_u[j] . u_t
__device__ float g_htraj[(TT + 1) * HDIM];   // h_t trajectory (h_traj[0] = h0)

// ---------------------------------------------------------------------------
// Kernel 1: precompute V[t][j] = b1[j] + sum_c W1[j][HDIM+c] * U[t][c]
// Fully parallel over t. blockDim = (64, 4).
// ---------------------------------------------------------------------------
__global__ void pre_kernel(const float* __restrict__ U,
                           const float* __restrict__ W1,
                           const float* __restrict__ b1) {
    int j = threadIdx.x;                       // hidden unit 0..63
    int t = blockIdx.x * blockDim.y + threadIdx.y;
    if (t >= TT) return;
    float acc = b1[j];
    const float* u = U + t * UDIM;
    const float* w = W1 + j * XDIM + HDIM;
#pragma unroll
    for (int c = 0; c < UDIM; c++)
        acc += w[c] * __ldg(u + c);
    g_V[t * HID + j] = acc;
}

// ---------------------------------------------------------------------------
// Kernel 2: the sequential scan. One CTA, 64 threads (2 warps).
// Lane j owns hidden unit j for z1/z2. For dh: i = j>>2, quarter q = j&3.
// Weights register-resident. z1/z2/h exchanged through shared memory.
// ---------------------------------------------------------------------------
__global__ void __launch_bounds__(64, 1)
scan_kernel(const float* __restrict__ W1,
            const float* __restrict__ W2,
            const float* __restrict__ b2,
            const float* __restrict__ W3,
            const float* __restrict__ b3,
            const float* __restrict__ h0,
            float* __restrict__ out) {
    const int j   = threadIdx.x;
    const int q   = j & 3;
    const int i16 = j >> 2;

    __shared__ __align__(16) float z1s[HID];
    __shared__ __align__(16) float z2s[HID];
    __shared__ __align__(16) float hs[HDIM];

    // --- load weights into registers (one-time) ---
    float w1h[HDIM];
#pragma unroll
    for (int c = 0; c < HDIM; c++) w1h[c] = W1[j * XDIM + c];

    float w2r[HID];
#pragma unroll
    for (int c = 0; c < HID; c++) w2r[c] = W2[j * HID + c];
    const float b2j = b2[j];

    float w3q[16];
#pragma unroll
    for (int m = 0; m < 16; m++) w3q[m] = W3[i16 * HID + q * 16 + m];
    const float b3i = (q == 0) ? b3[i16] : 0.0f;

    float h[HDIM];
#pragma unroll
    for (int c = 0; c < HDIM; c++) h[c] = h0[c];

    if (j < HDIM) g_htraj[j] = h[j];          // h_traj[0] = h0

    const float dt = (float)(5.0 / 60.0);

    const float* vp = g_V + HID + j;           // points at V[t+1][j]
    float vcur = g_V[j];                       // V[0][j]

#pragma unroll 1
    for (int t = 0; t < TT; t++) {
        // prefetch next V early — consumed ~500 cycles later
        float vnext = __ldg(vp);
        vp += HID;

        // ---- z1 = tanh(W1_h . h + V[t][j]) ----
        float a0 = vcur, a1 = 0.f, a2 = 0.f, a3 = 0.f;
#pragma unroll
        for (int c = 0; c < HDIM; c += 4) {
            a0 += w1h[c + 0] * h[c + 0];
            a1 += w1h[c + 1] * h[c + 1];
            a2 += w1h[c + 2] * h[c + 2];
            a3 += w1h[c + 3] * h[c + 3];
        }
        float z1 = tanhf((a0 + a1) + (a2 + a3));
        z1s[j] = z1;
        __syncthreads();

        // ---- z2 = tanh(W2 . z1 + b2) ----
        float c0 = b2j, c1 = 0.f, c2 = 0.f, c3 = 0.f;
        const float4* z14 = (const float4*)z1s;
#pragma unroll
        for (int c = 0; c < 16; c++) {
            float4 z = z14[c];
            c0 += w2r[4 * c + 0] * z.x;
            c1 += w2r[4 * c + 1] * z.y;
            c2 += w2r[4 * c + 2] * z.z;
            c3 += w2r[4 * c + 3] * z.w;
        }
        float z2 = tanhf((c0 + c1) + (c2 + c3));
        z2s[j] = z2;
        __syncthreads();

        // ---- dh[i16] partial over quarter q, then 4-lane butterfly ----
        float p0 = 0.f, p1 = 0.f, p2 = 0.f, p3 = 0.f;
        const float4* z24 = (const float4*)(z2s + q * 16);
#pragma unroll
        for (int c = 0; c < 4; c++) {
            float4 z = z24[c];
            p0 += w3q[4 * c + 0] * z.x;
            p1 += w3q[4 * c + 1] * z.y;
            p2 += w3q[4 * c + 2] * z.z;
            p3 += w3q[4 * c + 3] * z.w;
        }
        float p = (p0 + p1) + (p2 + p3);
        p += __shfl_xor_sync(0xffffffffu, p, 1);
        p += __shfl_xor_sync(0xffffffffu, p, 2);

        if (q == 0) {
            float hn = h[i16] + dt * (p + b3i);
            hs[i16] = hn;
            g_htraj[(t + 1) * HDIM + i16] = hn;   // fire-and-forget
        }
        __syncthreads();

        // ---- broadcast h back to all lanes ----
        const float4* h4 = (const float4*)hs;
#pragma unroll
        for (int c = 0; c < 4; c++) {
            float4 hv = h4[c];
            h[4 * c + 0] = hv.x;
            h[4 * c + 1] = hv.y;
            h[4 * c + 2] = hv.z;
            h[4 * c + 3] = hv.w;
        }
        vcur = vnext;
    }

    // final state hT -> out[3T .. 3T+16)
    if (j < HDIM) out[3 * TT + j] = h[j];
}

// ---------------------------------------------------------------------------
// Kernel 3: readouts from the stored trajectory. Fully parallel over t.
// delay[t] = h_t.wd + bd ; taxi[t] = h_t.wt + bt ; loglam[t] = h_t.wc + bc
// ---------------------------------------------------------------------------
__global__ void readout_kernel(const float* __restrict__ wd, const float* __restrict__ bd,
                               const float* __restrict__ wt, const float* __restrict__ bt,
                               const float* __restrict__ wc, const float* __restrict__ bc,
                               float* __restrict__ out) {
    int t = blockIdx.x * blockDim.x + threadIdx.x;
    if (t >= TT) return;

    float vd[HDIM], vt[HDIM], vc[HDIM];
#pragma unroll
    for (int k = 0; k < HDIM; k++) {
        vd[k] = __ldg(wd + k);
        vt[k] = __ldg(wt + k);
        vc[k] = __ldg(wc + k);
    }
    float d = __ldg(bd), x = __ldg(bt), c = __ldg(bc);
    const float4* h4 = (const float4*)(g_htraj + t * HDIM);
#pragma unroll
    for (int k = 0; k < 4; k++) {
        float4 hv = h4[k];
        d += hv.x * vd[4 * k] + hv.y * vd[4 * k + 1] + hv.z * vd[4 * k + 2] + hv.w * vd[4 * k + 3];
        x += hv.x * vt[4 * k] + hv.y * vt[4 * k + 1] + hv.z * vt[4 * k + 2] + hv.w * vt[4 * k + 3];
        c += hv.x * vc[4 * k] + hv.y * vc[4 * k + 1] + hv.z * vc[4 * k + 2] + hv.w * vc[4 * k + 3];
    }
    out[t]          = d;
    out[TT + t]     = x;
    out[2 * TT + t] = c;
}

// ---------------------------------------------------------------------------
extern "C" void kernel_launch(void* const* d_in, const int* in_sizes, int n_in,
                              void* d_out, int out_size) {
    const float* U  = (const float*)d_in[0];
    const float* W1 = (const float*)d_in[1];
    const float* b1 = (const float*)d_in[2];
    const float* W2 = (const float*)d_in[3];
    const float* b2 = (const float*)d_in[4];
    const float* W3 = (const float*)d_in[5];
    const float* b3 = (const float*)d_in[6];
    const float* wd = (const float*)d_in[7];
    const float* bd = (const float*)d_in[8];
    const float* wt = (const float*)d_in[9];
    const float* bt = (const float*)d_in[10];
    const float* wc = (const float*)d_in[11];
    const float* bc = (const float*)d_in[12];
    const float* h0 = (const float*)d_in[13];
    float* out = (float*)d_out;

    dim3 pb(HID, 4);
    pre_kernel<<<(TT + 3) / 4, pb>>>(U, W1, b1);
    scan_kernel<<<1, HID>>>(W1, W2, b2, W3, b3, h0, out);
    readout_kernel<<<(TT + 127) / 128, 128>>>(wd, bd, wt, bt, wc, bc, out);
}